// round 3
// baseline (speedup 1.0000x reference)
#include <cuda_runtime.h>
#include <math.h>

#define NN 4096
#define EE 128
#define HH 8
#define DD 16
#define TT 6
#define NEDGE 65536
#define RR 12
#define TPB 384

typedef unsigned long long u64;

__device__ float g_Q[NN*EE];
__device__ float g_K[NN*EE];
__device__ float g_V[NN*EE];
__device__ float g_O[NN*EE];
__device__ int g_tcount[TT], g_tptr[TT+1], g_tfill[TT];
__device__ int g_nodes[NN];
__device__ int g_ecount[NN], g_eptr[NN+1], g_efill[NN];
__device__ unsigned g_epk[NEDGE];

__device__ __forceinline__ u64 pk2(float x, float y){
    u64 r; asm("mov.b64 %0, {%1,%2};" : "=l"(r) : "f"(x), "f"(y)); return r;
}
__device__ __forceinline__ void up2(u64 v, float &x, float &y){
    asm("mov.b64 {%0,%1}, %2;" : "=f"(x), "=f"(y) : "l"(v));
}
__device__ __forceinline__ u64 ffma2(u64 a, u64 b, u64 c){
    u64 d; asm("fma.rn.f32x2 %0, %1, %2, %3;" : "=l"(d) : "l"(a), "l"(b), "l"(c)); return d;
}
__device__ __forceinline__ float wsum(float v){
    #pragma unroll
    for (int o = 16; o; o >>= 1) v += __shfl_xor_sync(0xffffffffu, v, o);
    return v;
}
__device__ __forceinline__ float wmax(float v){
    #pragma unroll
    for (int o = 16; o; o >>= 1) v = fmaxf(v, __shfl_xor_sync(0xffffffffu, v, o));
    return v;
}

__global__ void zero_k(){
    int i = blockIdx.x * blockDim.x + threadIdx.x;
    if (i < NN) g_ecount[i] = 0;
    else if (i < 2*NN) g_efill[i-NN] = 0;
    else if (i < 2*NN+TT) g_tcount[i-2*NN] = 0;
    else if (i < 2*NN+2*TT) g_tfill[i-2*NN-TT] = 0;
}

__global__ void count_k(const int* __restrict__ ntypes, const int* __restrict__ eidx){
    int i = blockIdx.x * blockDim.x + threadIdx.x;
    if (i < NN) atomicAdd(&g_tcount[ntypes[i]], 1);
    else if (i < NN + NEDGE) atomicAdd(&g_ecount[eidx[NEDGE + (i-NN)]], 1);
}

__global__ void scan_k(){
    __shared__ int wsums[32];
    const int tid = threadIdx.x, lane = tid & 31, wid = tid >> 5;
    const int base = tid * 4;
    int c0 = g_ecount[base], c1 = g_ecount[base+1], c2 = g_ecount[base+2], c3 = g_ecount[base+3];
    int i0 = c0, i1 = i0+c1, i2 = i1+c2, i3 = i2+c3;
    int x = i3;
    #pragma unroll
    for (int d = 1; d < 32; d <<= 1){
        int y = __shfl_up_sync(0xffffffffu, x, d);
        if (lane >= d) x += y;
    }
    if (lane == 31) wsums[wid] = x;
    __syncthreads();
    if (wid == 0){
        int v = wsums[lane];
        #pragma unroll
        for (int d = 1; d < 32; d <<= 1){
            int y = __shfl_up_sync(0xffffffffu, v, d);
            if (lane >= d) v += y;
        }
        wsums[lane] = v;
    }
    __syncthreads();
    int woff = (wid == 0) ? 0 : wsums[wid-1];
    int texcl = woff + (x - i3);
    g_eptr[base]   = texcl;
    g_eptr[base+1] = texcl + i0;
    g_eptr[base+2] = texcl + i1;
    g_eptr[base+3] = texcl + i2;
    if (tid == 1023) g_eptr[NN] = texcl + i3;
    if (tid == 0){
        int s = 0;
        #pragma unroll
        for (int t = 0; t < TT; t++){ g_tptr[t] = s; s += g_tcount[t]; }
        g_tptr[TT] = s;
    }
}

__global__ void scatter_k(const int* __restrict__ ntypes, const int* __restrict__ eidx,
                          const int* __restrict__ etypes){
    int i = blockIdx.x * blockDim.x + threadIdx.x;
    if (i < NN){
        int t = ntypes[i];
        g_nodes[g_tptr[t] + atomicAdd(&g_tfill[t], 1)] = i;
    } else if (i < NN + NEDGE){
        int e = i - NN;
        int tgt = eidx[NEDGE + e];
        int pos = g_eptr[tgt] + atomicAdd(&g_efill[tgt], 1);
        g_epk[pos] = (unsigned)eidx[e] | ((unsigned)etypes[e] << 12) | ((unsigned)tgt << 14);
    }
}

__global__ void __launch_bounds__(128) proj_k(
    const float* __restrict__ xq, const float* __restrict__ xk, const float* __restrict__ xv,
    const float* __restrict__ Wq, const float* __restrict__ bq,
    const float* __restrict__ Wk, const float* __restrict__ bk,
    const float* __restrict__ Wv, const float* __restrict__ bv){
    const int t = blockIdx.y;
    const int start = g_tptr[t] + blockIdx.x * 16;
    const int end = g_tptr[t+1];
    if (start >= end) return;
    const int cnt = min(16, end - start);
    __shared__ int nid[16];
    __shared__ float sq[128*17], sk[128*17], sv[128*17];
    const int f = threadIdx.x;
    if (f < 16) nid[f] = (f < cnt) ? g_nodes[start + f] : -1;
    __syncthreads();
    #pragma unroll
    for (int n = 0; n < 16; n++){
        int row = nid[n];
        float a=0.f,b=0.f,c=0.f;
        if (row >= 0){
            a = xq[(size_t)row*EE + f];
            b = xk[(size_t)row*EE + f];
            c = xv[(size_t)row*EE + f];
        }
        sq[f*17+n]=a; sk[f*17+n]=b; sv[f*17+n]=c;
    }
    __syncthreads();
    float aq[16], ak[16], av[16];
    #pragma unroll
    for (int n = 0; n < 16; n++){ aq[n]=0.f; ak[n]=0.f; av[n]=0.f; }
    const float* wq = Wq + (size_t)t*EE*EE;
    const float* wk = Wk + (size_t)t*EE*EE;
    const float* wv = Wv + (size_t)t*EE*EE;
    for (int e = 0; e < EE; e++){
        float q = wq[e*EE+f], k = wk[e*EE+f], v = wv[e*EE+f];
        #pragma unroll
        for (int n = 0; n < 16; n++){
            aq[n] = fmaf(sq[e*17+n], q, aq[n]);
            ak[n] = fmaf(sk[e*17+n], k, ak[n]);
            av[n] = fmaf(sv[e*17+n], v, av[n]);
        }
    }
    float bqv = bq[t*EE+f], bkv = bk[t*EE+f], bvv = bv[t*EE+f];
    for (int n = 0; n < cnt; n++){
        int row = nid[n];
        g_Q[(size_t)row*EE+f] = aq[n] + bqv;
        g_K[(size_t)row*EE+f] = ak[n] + bkv;
        g_V[(size_t)row*EE+f] = av[n] + bvv;
    }
}

// SMEM: S 12*4096 f32 (196608B) | vsm 256*9 u64 (18432B) | qsm 16*6 u64 (768B)
#define SM_V 196608
#define SM_Q (196608 + 18432)
#define SM_TOTAL (196608 + 18432 + 768)

__global__ void __launch_bounds__(TPB, 1) attn_k(const float* __restrict__ eb,
                                                 float* __restrict__ attn){
    extern __shared__ unsigned char smraw[];
    float* S   = (float*)smraw;
    u64*   vsm = (u64*)(smraw + SM_V);
    u64*   qsm = (u64*)(smraw + SM_Q);

    const int tid = threadIdx.x, lane = tid & 31, w = tid >> 5;
    const int h = blockIdx.y;
    const int i0 = blockIdx.x * RR;
    const int rows = min(RR, NN - i0);

    // Q tile, pre-scaled by 1/sqrt(D)
    for (int t = tid; t < 192; t += TPB){
        int r = t >> 4, d = t & 15;
        float q = (r < rows) ? g_Q[(size_t)(i0+r)*EE + h*DD + d] * 0.25f : 0.f;
        ((float*)qsm)[(d*6 + (r>>1))*2 + (r&1)] = q;
    }
    __syncthreads();

    // P1: scores = (Q/sqrtD) K^T
    for (int j = tid; j < 2048; j += TPB){
        const float4* kpa = (const float4*)(g_K + (size_t)j*EE + h*DD);
        const float4* kpb = (const float4*)(g_K + (size_t)(j+2048)*EE + h*DD);
        float4 a0=kpa[0],a1=kpa[1],a2=kpa[2],a3=kpa[3];
        float4 b0=kpb[0],b1=kpb[1],b2=kpb[2],b3=kpb[3];
        float ka[16]={a0.x,a0.y,a0.z,a0.w,a1.x,a1.y,a1.z,a1.w,
                      a2.x,a2.y,a2.z,a2.w,a3.x,a3.y,a3.z,a3.w};
        float kb[16]={b0.x,b0.y,b0.z,b0.w,b1.x,b1.y,b1.z,b1.w,
                      b2.x,b2.y,b2.z,b2.w,b3.x,b3.y,b3.z,b3.w};
        u64 acc[6], bcc[6];
        #pragma unroll
        for (int rp = 0; rp < 6; rp++){ acc[rp]=0ull; bcc[rp]=0ull; }
        #pragma unroll
        for (int d = 0; d < 16; d++){
            u64 ka2 = pk2(ka[d], ka[d]);
            u64 kb2 = pk2(kb[d], kb[d]);
            #pragma unroll
            for (int rp = 0; rp < 6; rp++){
                u64 q2 = qsm[d*6 + rp];
                acc[rp] = ffma2(q2, ka2, acc[rp]);
                bcc[rp] = ffma2(q2, kb2, bcc[rp]);
            }
        }
        #pragma unroll
        for (int rp = 0; rp < 6; rp++){
            float x, y;
            up2(acc[rp], x, y);
            S[(2*rp)*NN + j]   = x;
            S[(2*rp+1)*NN + j] = y;
            up2(bcc[rp], x, y);
            S[(2*rp)*NN + j + 2048]   = x;
            S[(2*rp+1)*NN + j + 2048] = y;
        }
    }
    __syncthreads();

    // P2: CSR edge bias (dup-safe scatter-add), eb hoisted to registers
    {
        float eb0 = eb[h], eb1 = eb[HH + h], eb2 = eb[2*HH + h];
        int e0 = g_eptr[i0], e1 = g_eptr[i0 + rows];
        for (int e = e0 + tid; e < e1; e += TPB){
            unsigned p = g_epk[e];
            int src = p & 0xFFF;
            int et  = (p >> 12) & 3;
            int r   = (int)(p >> 14) - i0;
            float b = (et == 0) ? eb0 : ((et == 1) ? eb1 : eb2);
            atomicAdd(&S[r*NN + src], b);
        }
    }
    __syncthreads();

    // prefetch V tile 0 into registers (in flight during softmax)
    u64 pf[6];
    #pragma unroll
    for (int it = 0; it < 6; it++){
        int t = tid + it*TPB;
        if (t < 2048){
            int j = t >> 3, dp = t & 7;
            float2 v2 = *(const float2*)(g_V + (size_t)j*EE + h*DD + dp*2);
            pf[it] = pk2(v2.x, v2.y);
        }
    }

    // P3: softmax per row (warp-per-row, float4), write attn
    if (w < rows){
        float4* S4 = (float4*)(S + (size_t)w*NN);
        float m = -1e30f;
        #pragma unroll 4
        for (int jb = lane; jb < 1024; jb += 32){
            float4 v = S4[jb];
            m = fmaxf(m, fmaxf(fmaxf(v.x, v.y), fmaxf(v.z, v.w)));
        }
        m = wmax(m);
        float s = 0.f;
        #pragma unroll 2
        for (int jb = lane; jb < 1024; jb += 32){
            float4 v = S4[jb];
            v.x = __expf(v.x - m); v.y = __expf(v.y - m);
            v.z = __expf(v.z - m); v.w = __expf(v.w - m);
            s += (v.x + v.y) + (v.z + v.w);
            S4[jb] = v;
        }
        s = wsum(s);
        float invs = 1.f / s;
        float4* arow = (float4*)(attn + (size_t)h*NN*NN + (size_t)(i0+w)*NN);
        #pragma unroll 2
        for (int jb = lane; jb < 1024; jb += 32){
            float4 v = S4[jb];
            v.x *= invs; v.y *= invs; v.z *= invs; v.w *= invs;
            S4[jb] = v;
            arow[jb] = v;
        }
    }
    // no sync needed: each warp consumes only its own row of S in P4

    // P4: out_h = P @ V_h, V double-buffered through registers
    u64 acc[8];
    #pragma unroll
    for (int dp = 0; dp < 8; dp++) acc[dp] = 0ull;
    for (int jt = 0; jt < NN; jt += 256){
        __syncthreads();   // vsm free (prev tile consumed / first entry)
        #pragma unroll
        for (int it = 0; it < 6; it++){
            int t = tid + it*TPB;
            if (t < 2048){
                int j = t >> 3, dp = t & 7;
                vsm[j*9 + dp] = pf[it];
            }
        }
        __syncthreads();   // vsm ready
        // prefetch next tile (hidden under compute below)
        if (jt + 256 < NN){
            #pragma unroll
            for (int it = 0; it < 6; it++){
                int t = tid + it*TPB;
                if (t < 2048){
                    int j = t >> 3, dp = t & 7;
                    float2 v2 = *(const float2*)(g_V + (size_t)(jt+256+j)*EE + h*DD + dp*2);
                    pf[it] = pk2(v2.x, v2.y);
                }
            }
        }
        if (w < rows){
            const float* Srow = S + (size_t)w*NN + jt;
            #pragma unroll
            for (int k = 0; k < 8; k++){
                int j = k*32 + lane;
                float p = Srow[j];
                u64 pp = pk2(p, p);
                #pragma unroll
                for (int dp = 0; dp < 8; dp++)
                    acc[dp] = ffma2(vsm[j*9 + dp], pp, acc[dp]);
            }
        }
    }
    if (w < rows){
        float fv[16];
        #pragma unroll
        for (int dp = 0; dp < 8; dp++) up2(acc[dp], fv[2*dp], fv[2*dp+1]);
        float outv = 0.f;
        #pragma unroll
        for (int d = 0; d < 16; d++){
            float sv = wsum(fv[d]);
            if (lane == d) outv = sv;
        }
        if (lane < 16) g_O[(size_t)(i0+w)*EE + h*DD + lane] = outv;
    }
}

__global__ void __launch_bounds__(128) out_k(const float* __restrict__ Wo,
                                             const float* __restrict__ bo,
                                             float* __restrict__ out){
    __shared__ float s[32*129];
    const int f = threadIdx.x;
    const int r0 = blockIdx.x * 32;
    for (int t = f; t < 32*128; t += 128){
        int n = t >> 7, e = t & 127;
        s[n*129 + e] = g_O[(size_t)(r0+n)*EE + e];
    }
    __syncthreads();
    float acc[32];
    float bv = bo[f];
    #pragma unroll
    for (int n = 0; n < 32; n++) acc[n] = bv;
    for (int e = 0; e < 128; e++){
        float wv = Wo[e*EE + f];
        #pragma unroll
        for (int n = 0; n < 32; n++) acc[n] = fmaf(s[n*129 + e], wv, acc[n]);
    }
    #pragma unroll
    for (int n = 0; n < 32; n++) out[(size_t)(r0+n)*EE + f] = acc[n];
}

extern "C" void kernel_launch(void* const* d_in, const int* in_sizes, int n_in,
                              void* d_out, int out_size){
    const float* query = (const float*)d_in[0];
    const float* key_  = (const float*)d_in[1];
    const float* value = (const float*)d_in[2];
    const float* Wq = (const float*)d_in[3];
    const float* bq = (const float*)d_in[4];
    const float* Wk = (const float*)d_in[5];
    const float* bk = (const float*)d_in[6];
    const float* Wv = (const float*)d_in[7];
    const float* bv = (const float*)d_in[8];
    const float* eb = (const float*)d_in[9];
    const float* Wo = (const float*)d_in[10];
    const float* bo = (const float*)d_in[11];
    const int* ntypes = (const int*)d_in[12];
    const int* eidx   = (const int*)d_in[13];
    const int* etypes = (const int*)d_in[14];
    float* out  = (float*)d_out;
    float* attn = out + (size_t)NN*EE;

    static bool attr_set = false;
    if (!attr_set){
        cudaFuncSetAttribute(attn_k, cudaFuncAttributeMaxDynamicSharedMemorySize, SM_TOTAL);
        attr_set = true;
    }

    zero_k<<<(2*NN + 2*TT + 255)/256, 256>>>();
    count_k<<<(NN + NEDGE + 255)/256, 256>>>(ntypes, eidx);
    scan_k<<<1, 1024>>>();
    scatter_k<<<(NN + NEDGE + 255)/256, 256>>>(ntypes, eidx, etypes);
    proj_k<<<dim3((NN + 15)/16, TT), 128>>>(query, key_, value, Wq, bq, Wk, bk, Wv, bv);
    attn_k<<<dim3((NN + RR - 1)/RR, HH), TPB, SM_TOTAL>>>(eb, attn);
    out_k<<<NN/32, 128>>>(Wo, bo, out);
}

// round 4
// speedup vs baseline: 1.5026x; 1.5026x over previous
#include <cuda_runtime.h>
#include <math.h>

#define NN 4096
#define EE 128
#define HH 8
#define DD 16
#define TT 6
#define NEDGE 65536
#define RR 12
#define TPB 512

typedef unsigned long long u64;

__device__ float g_Qh[HH*NN*DD];
__device__ float g_Kh[HH*NN*DD];
__device__ float g_Vh[HH*NN*DD];
__device__ float g_O[NN*EE];
__device__ int g_tcount[TT], g_tptr[TT+1], g_tfill[TT];
__device__ int g_nodes[NN];
__device__ int g_ecount[NN], g_eptr[NN+1], g_efill[NN];
__device__ unsigned g_epk[NEDGE];

__device__ __forceinline__ u64 pk2(float x, float y){
    u64 r; asm("mov.b64 %0, {%1,%2};" : "=l"(r) : "f"(x), "f"(y)); return r;
}
__device__ __forceinline__ void up2(u64 v, float &x, float &y){
    asm("mov.b64 {%0,%1}, %2;" : "=f"(x), "=f"(y) : "l"(v));
}
__device__ __forceinline__ u64 ffma2(u64 a, u64 b, u64 c){
    u64 d; asm("fma.rn.f32x2 %0, %1, %2, %3;" : "=l"(d) : "l"(a), "l"(b), "l"(c)); return d;
}
__device__ __forceinline__ float wsum(float v){
    #pragma unroll
    for (int o = 16; o; o >>= 1) v += __shfl_xor_sync(0xffffffffu, v, o);
    return v;
}
__device__ __forceinline__ float wmax(float v){
    #pragma unroll
    for (int o = 16; o; o >>= 1) v = fmaxf(v, __shfl_xor_sync(0xffffffffu, v, o));
    return v;
}

__global__ void zero_k(){
    int i = blockIdx.x * blockDim.x + threadIdx.x;
    if (i < NN) g_ecount[i] = 0;
    else if (i < 2*NN) g_efill[i-NN] = 0;
    else if (i < 2*NN+TT) g_tcount[i-2*NN] = 0;
    else if (i < 2*NN+2*TT) g_tfill[i-2*NN-TT] = 0;
}

__global__ void count_k(const int* __restrict__ ntypes, const int* __restrict__ eidx){
    int i = blockIdx.x * blockDim.x + threadIdx.x;
    if (i < NN) atomicAdd(&g_tcount[ntypes[i]], 1);
    else if (i < NN + NEDGE) atomicAdd(&g_ecount[eidx[NEDGE + (i-NN)]], 1);
}

__global__ void scan_k(){
    __shared__ int wsums[32];
    const int tid = threadIdx.x, lane = tid & 31, wid = tid >> 5;
    const int base = tid * 4;
    int c0 = g_ecount[base], c1 = g_ecount[base+1], c2 = g_ecount[base+2], c3 = g_ecount[base+3];
    int i0 = c0, i1 = i0+c1, i2 = i1+c2, i3 = i2+c3;
    int x = i3;
    #pragma unroll
    for (int d = 1; d < 32; d <<= 1){
        int y = __shfl_up_sync(0xffffffffu, x, d);
        if (lane >= d) x += y;
    }
    if (lane == 31) wsums[wid] = x;
    __syncthreads();
    if (wid == 0){
        int v = wsums[lane];
        #pragma unroll
        for (int d = 1; d < 32; d <<= 1){
            int y = __shfl_up_sync(0xffffffffu, v, d);
            if (lane >= d) v += y;
        }
        wsums[lane] = v;
    }
    __syncthreads();
    int woff = (wid == 0) ? 0 : wsums[wid-1];
    int texcl = woff + (x - i3);
    g_eptr[base]   = texcl;
    g_eptr[base+1] = texcl + i0;
    g_eptr[base+2] = texcl + i1;
    g_eptr[base+3] = texcl + i2;
    if (tid == 1023) g_eptr[NN] = texcl + i3;
    if (tid == 0){
        int s = 0;
        #pragma unroll
        for (int t = 0; t < TT; t++){ g_tptr[t] = s; s += g_tcount[t]; }
        g_tptr[TT] = s;
    }
}

__global__ void scatter_k(const int* __restrict__ ntypes, const int* __restrict__ eidx,
                          const int* __restrict__ etypes){
    int i = blockIdx.x * blockDim.x + threadIdx.x;
    if (i < NN){
        int t = ntypes[i];
        g_nodes[g_tptr[t] + atomicAdd(&g_tfill[t], 1)] = i;
    } else if (i < NN + NEDGE){
        int e = i - NN;
        int tgt = eidx[NEDGE + e];
        int pos = g_eptr[tgt] + atomicAdd(&g_efill[tgt], 1);
        g_epk[pos] = (unsigned)eidx[e] | ((unsigned)etypes[e] << 12) | ((unsigned)tgt << 14);
    }
}

__global__ void __launch_bounds__(128) proj_k(
    const float* __restrict__ xq, const float* __restrict__ xk, const float* __restrict__ xv,
    const float* __restrict__ Wq, const float* __restrict__ bq,
    const float* __restrict__ Wk, const float* __restrict__ bk,
    const float* __restrict__ Wv, const float* __restrict__ bv){
    const int t = blockIdx.y;
    const int start = g_tptr[t] + blockIdx.x * 16;
    const int end = g_tptr[t+1];
    if (start >= end) return;
    const int cnt = min(16, end - start);
    __shared__ int nid[16];
    __shared__ float sq[128*17], sk[128*17], sv[128*17];
    const int f = threadIdx.x;
    if (f < 16) nid[f] = (f < cnt) ? g_nodes[start + f] : -1;
    __syncthreads();
    #pragma unroll
    for (int n = 0; n < 16; n++){
        int row = nid[n];
        float a=0.f,b=0.f,c=0.f;
        if (row >= 0){
            a = xq[(size_t)row*EE + f];
            b = xk[(size_t)row*EE + f];
            c = xv[(size_t)row*EE + f];
        }
        sq[f*17+n]=a; sk[f*17+n]=b; sv[f*17+n]=c;
    }
    __syncthreads();
    float aq[16], ak[16], av[16];
    #pragma unroll
    for (int n = 0; n < 16; n++){ aq[n]=0.f; ak[n]=0.f; av[n]=0.f; }
    const float* wq = Wq + (size_t)t*EE*EE;
    const float* wk = Wk + (size_t)t*EE*EE;
    const float* wv = Wv + (size_t)t*EE*EE;
    for (int e = 0; e < EE; e++){
        float q = wq[e*EE+f], k = wk[e*EE+f], v = wv[e*EE+f];
        #pragma unroll
        for (int n = 0; n < 16; n++){
            aq[n] = fmaf(sq[e*17+n], q, aq[n]);
            ak[n] = fmaf(sk[e*17+n], k, ak[n]);
            av[n] = fmaf(sv[e*17+n], v, av[n]);
        }
    }
    float bqv = bq[t*EE+f], bkv = bk[t*EE+f], bvv = bv[t*EE+f];
    const int fh = f >> 4, fd = f & 15;
    for (int n = 0; n < cnt; n++){
        int row = nid[n];
        size_t idx = ((size_t)fh*NN + row)*DD + fd;
        g_Qh[idx] = aq[n] + bqv;
        g_Kh[idx] = ak[n] + bkv;
        g_Vh[idx] = av[n] + bvv;
    }
}

// SMEM: S 12*4096 f32 (196608B) | vsm 256*10 u64 (20480B) | qsm 16*6 u64 (768B) | osum 192 f32 (768B)
#define SM_V 196608
#define SM_Q (196608 + 20480)
#define SM_R (196608 + 20480 + 768)
#define SM_TOTAL (196608 + 20480 + 768 + 768)

__global__ void __launch_bounds__(TPB, 1) attn_k(const float* __restrict__ eb,
                                                 float* __restrict__ attn){
    extern __shared__ unsigned char smraw[];
    float* S    = (float*)smraw;
    u64*   vsm  = (u64*)(smraw + SM_V);
    u64*   qsm  = (u64*)(smraw + SM_Q);
    float* osum = (float*)(smraw + SM_R);

    const int tid = threadIdx.x, lane = tid & 31, w = tid >> 5;
    const int h = blockIdx.y;
    const int i0 = blockIdx.x * RR;
    const int rows = min(RR, NN - i0);
    const float* Kh = g_Kh + (size_t)h*NN*DD;
    const float* Vh = g_Vh + (size_t)h*NN*DD;

    // Q tile, pre-scaled by 1/sqrt(D); pad rows -> 0
    for (int t = tid; t < 192; t += TPB){
        int r = t >> 4, d = t & 15;
        float q = (r < rows) ? g_Qh[((size_t)h*NN + i0 + r)*DD + d] * 0.25f : 0.f;
        ((float*)qsm)[(d*6 + (r>>1))*2 + (r&1)] = q;
    }
    if (tid < 192) osum[tid] = 0.f;
    __syncthreads();

    // P1: scores = (Q/sqrtD) K^T ; K per-head, fully coalesced
    for (int j = tid; j < 2048; j += TPB){
        const float4* kpa = (const float4*)(Kh + (size_t)j*DD);
        const float4* kpb = (const float4*)(Kh + (size_t)(j+2048)*DD);
        float4 a0=kpa[0],a1=kpa[1],a2=kpa[2],a3=kpa[3];
        float4 b0=kpb[0],b1=kpb[1],b2=kpb[2],b3=kpb[3];
        float ka[16]={a0.x,a0.y,a0.z,a0.w,a1.x,a1.y,a1.z,a1.w,
                      a2.x,a2.y,a2.z,a2.w,a3.x,a3.y,a3.z,a3.w};
        float kb[16]={b0.x,b0.y,b0.z,b0.w,b1.x,b1.y,b1.z,b1.w,
                      b2.x,b2.y,b2.z,b2.w,b3.x,b3.y,b3.z,b3.w};
        u64 acc[6], bcc[6];
        #pragma unroll
        for (int rp = 0; rp < 6; rp++){ acc[rp]=0ull; bcc[rp]=0ull; }
        #pragma unroll
        for (int d = 0; d < 16; d++){
            u64 ka2 = pk2(ka[d], ka[d]);
            u64 kb2 = pk2(kb[d], kb[d]);
            #pragma unroll
            for (int rp = 0; rp < 6; rp++){
                u64 q2 = qsm[d*6 + rp];
                acc[rp] = ffma2(q2, ka2, acc[rp]);
                bcc[rp] = ffma2(q2, kb2, bcc[rp]);
            }
        }
        #pragma unroll
        for (int rp = 0; rp < 6; rp++){
            float x, y;
            up2(acc[rp], x, y);
            S[(2*rp)*NN + j]   = x;
            S[(2*rp+1)*NN + j] = y;
            up2(bcc[rp], x, y);
            S[(2*rp)*NN + j + 2048]   = x;
            S[(2*rp+1)*NN + j + 2048] = y;
        }
    }
    __syncthreads();

    // P2: CSR edge bias (dup-safe scatter-add)
    {
        float eb0 = eb[h], eb1 = eb[HH + h], eb2 = eb[2*HH + h];
        int e0 = g_eptr[i0], e1 = g_eptr[i0 + rows];
        for (int e = e0 + tid; e < e1; e += TPB){
            unsigned p = g_epk[e];
            int src = p & 0xFFF;
            int et  = (p >> 12) & 3;
            int r   = (int)(p >> 14) - i0;
            float b = (et == 0) ? eb0 : ((et == 1) ? eb1 : eb2);
            atomicAdd(&S[r*NN + src], b);
        }
    }
    __syncthreads();

    // P3: softmax per row (warp-per-row), write attn (scalar, R2-style)
    if (w < rows){
        float* Srow = S + (size_t)w*NN;
        float m = -1e30f;
        for (int j = lane; j < NN; j += 32) m = fmaxf(m, Srow[j]);
        m = wmax(m);
        float s = 0.f;
        for (int j = lane; j < NN; j += 32){
            float e = __expf(Srow[j] - m);
            Srow[j] = e; s += e;
        }
        s = wsum(s);
        float invs = 1.f / s;
        float* arow = attn + (size_t)h*NN*NN + (size_t)(i0+w)*NN;
        for (int j = lane; j < NN; j += 32){
            float p = Srow[j] * invs;
            Srow[j] = p;
            arow[j] = p;
        }
    }

    // P4: out = P @ V. 16 warps = 4 j-splits x 4 row-groups (3 rows each).
    // V tile (256 rows x 16d) staged in smem, u64 stride 10 -> dp-pair LDS.128 conflict-free.
    const int jsplit = w >> 2;          // 0..3 : which 64-j slice of each 256 tile
    const int rg     = (w & 3) * 3;     // row group base: 0,3,6,9
    u64 acc[3][8];
    #pragma unroll
    for (int r = 0; r < 3; r++)
        #pragma unroll
        for (int dp = 0; dp < 8; dp++) acc[r][dp] = 0ull;

    for (int jt = 0; jt < NN; jt += 256){
        __syncthreads();
        for (int t = tid; t < 2048; t += TPB){
            int j = t >> 3, dp = t & 7;
            float2 v2 = *(const float2*)(Vh + (size_t)(jt+j)*DD + dp*2);
            vsm[j*10 + dp] = pk2(v2.x, v2.y);
        }
        __syncthreads();
        #pragma unroll
        for (int jj = 0; jj < 2; jj++){
            int j = jsplit*64 + jj*32 + lane;
            const unsigned char* vb = (const unsigned char*)vsm + j*80;
            u64 vv[8];
            #pragma unroll
            for (int q = 0; q < 4; q++){
                float4 f4 = *(const float4*)(vb + q*16);
                vv[2*q]   = pk2(f4.x, f4.y);
                vv[2*q+1] = pk2(f4.z, f4.w);
            }
            #pragma unroll
            for (int r = 0; r < 3; r++){
                float p = S[(rg + r)*NN + jt + j];
                u64 pp = pk2(p, p);
                #pragma unroll
                for (int dp = 0; dp < 8; dp++)
                    acc[r][dp] = ffma2(vv[dp], pp, acc[r][dp]);
            }
        }
    }
    // reduce: lane-sum per (r,d) -> lane d holds it -> atomic add across 4 j-split warps
    #pragma unroll
    for (int r = 0; r < 3; r++){
        float fv[16];
        #pragma unroll
        for (int dp = 0; dp < 8; dp++) up2(acc[r][dp], fv[2*dp], fv[2*dp+1]);
        float outv = 0.f;
        #pragma unroll
        for (int d = 0; d < 16; d++){
            float sv = wsum(fv[d]);
            if (lane == d) outv = sv;
        }
        if (lane < 16) atomicAdd(&osum[(rg + r)*16 + lane], outv);
    }
    __syncthreads();
    if (tid < 192){
        int r = tid >> 4, d = tid & 15;
        if (r < rows) g_O[(size_t)(i0+r)*EE + h*DD + d] = osum[tid];
    }
}

__global__ void __launch_bounds__(128) out_k(const float* __restrict__ Wo,
                                             const float* __restrict__ bo,
                                             float* __restrict__ out){
    __shared__ float s[32*129];
    const int f = threadIdx.x;
    const int r0 = blockIdx.x * 32;
    for (int t = f; t < 32*128; t += 128){
        int n = t >> 7, e = t & 127;
        s[n*129 + e] = g_O[(size_t)(r0+n)*EE + e];
    }
    __syncthreads();
    float acc[32];
    float bv = bo[f];
    #pragma unroll
    for (int n = 0; n < 32; n++) acc[n] = bv;
    for (int e = 0; e < 128; e++){
        float wv = Wo[e*EE + f];
        #pragma unroll
        for (int n = 0; n < 32; n++) acc[n] = fmaf(s[n*129 + e], wv, acc[n]);
    }
    #pragma unroll
    for (int n = 0; n < 32; n++) out[(size_t)(r0+n)*EE + f] = acc[n];
}

extern "C" void kernel_launch(void* const* d_in, const int* in_sizes, int n_in,
                              void* d_out, int out_size){
    const float* query = (const float*)d_in[0];
    const float* key_  = (const float*)d_in[1];
    const float* value = (const float*)d_in[2];
    const float* Wq = (const float*)d_in[3];
    const float* bq = (const float*)d_in[4];
    const float* Wk = (const float*)d_in[5];
    const float* bk = (const float*)d_in[6];
    const float* Wv = (const float*)d_in[7];
    const float* bv = (const float*)d_in[8];
    const float* eb = (const float*)d_in[9];
    const float* Wo = (const float*)d_in[10];
    const float* bo = (const float*)d_in[11];
    const int* ntypes = (const int*)d_in[12];
    const int* eidx   = (const int*)d_in[13];
    const int* etypes = (const int*)d_in[14];
    float* out  = (float*)d_out;
    float* attn = out + (size_t)NN*EE;

    static bool attr_set = false;
    if (!attr_set){
        cudaFuncSetAttribute(attn_k, cudaFuncAttributeMaxDynamicSharedMemorySize, SM_TOTAL);
        attr_set = true;
    }

    zero_k<<<(2*NN + 2*TT + 255)/256, 256>>>();
    count_k<<<(NN + NEDGE + 255)/256, 256>>>(ntypes, eidx);
    scan_k<<<1, 1024>>>();
    scatter_k<<<(NN + NEDGE + 255)/256, 256>>>(ntypes, eidx, etypes);
    proj_k<<<dim3((NN + 15)/16, TT), 128>>>(query, key_, value, Wq, bq, Wk, bk, Wv, bv);
    attn_k<<<dim3((NN + RR - 1)/RR, HH), TPB, SM_TOTAL>>>(eb, attn);
    out_k<<<NN/32, 128>>>(Wo, bo, out);
}

// round 5
// speedup vs baseline: 2.0084x; 1.3367x over previous
#include <cuda_runtime.h>
#include <math.h>

#define NN 4096
#define EE 128
#define HH 8
#define DD 16
#define TT 6
#define NEDGE 65536
#define RR 12
#define TPB 512

typedef unsigned long long u64;

__device__ float g_Qh[HH*NN*DD];
__device__ float g_Kh[HH*NN*DD];
__device__ float g_Vh[HH*NN*DD];
__device__ float g_O[NN*EE];
__device__ int g_tcount[TT], g_tptr[TT+1], g_tfill[TT];
__device__ int g_nodes[NN];
__device__ int g_ecount[NN], g_eptr[NN+1], g_efill[NN];
__device__ unsigned g_epk[NEDGE];

__device__ __forceinline__ u64 pk2(float x, float y){
    u64 r; asm("mov.b64 %0, {%1,%2};" : "=l"(r) : "f"(x), "f"(y)); return r;
}
__device__ __forceinline__ void up2(u64 v, float &x, float &y){
    asm("mov.b64 {%0,%1}, %2;" : "=f"(x), "=f"(y) : "l"(v));
}
__device__ __forceinline__ u64 ffma2(u64 a, u64 b, u64 c){
    u64 d; asm("fma.rn.f32x2 %0, %1, %2, %3;" : "=l"(d) : "l"(a), "l"(b), "l"(c)); return d;
}
__device__ __forceinline__ float wsum(float v){
    #pragma unroll
    for (int o = 16; o; o >>= 1) v += __shfl_xor_sync(0xffffffffu, v, o);
    return v;
}
__device__ __forceinline__ float wmax(float v){
    #pragma unroll
    for (int o = 16; o; o >>= 1) v = fmaxf(v, __shfl_xor_sync(0xffffffffu, v, o));
    return v;
}

__global__ void zero_k(){
    int i = blockIdx.x * blockDim.x + threadIdx.x;
    if (i < NN) g_ecount[i] = 0;
    else if (i < 2*NN) g_efill[i-NN] = 0;
    else if (i < 2*NN+TT) g_tcount[i-2*NN] = 0;
    else if (i < 2*NN+2*TT) g_tfill[i-2*NN-TT] = 0;
}

__global__ void count_k(const int* __restrict__ ntypes, const int* __restrict__ eidx){
    int i = blockIdx.x * blockDim.x + threadIdx.x;
    if (i < NN) atomicAdd(&g_tcount[ntypes[i]], 1);
    else if (i < NN + NEDGE) atomicAdd(&g_ecount[eidx[NEDGE + (i-NN)]], 1);
}

__global__ void scan_k(){
    __shared__ int wsums[32];
    const int tid = threadIdx.x, lane = tid & 31, wid = tid >> 5;
    const int base = tid * 4;
    int c0 = g_ecount[base], c1 = g_ecount[base+1], c2 = g_ecount[base+2], c3 = g_ecount[base+3];
    int i0 = c0, i1 = i0+c1, i2 = i1+c2, i3 = i2+c3;
    int x = i3;
    #pragma unroll
    for (int d = 1; d < 32; d <<= 1){
        int y = __shfl_up_sync(0xffffffffu, x, d);
        if (lane >= d) x += y;
    }
    if (lane == 31) wsums[wid] = x;
    __syncthreads();
    if (wid == 0){
        int v = wsums[lane];
        #pragma unroll
        for (int d = 1; d < 32; d <<= 1){
            int y = __shfl_up_sync(0xffffffffu, v, d);
            if (lane >= d) v += y;
        }
        wsums[lane] = v;
    }
    __syncthreads();
    int woff = (wid == 0) ? 0 : wsums[wid-1];
    int texcl = woff + (x - i3);
    g_eptr[base]   = texcl;
    g_eptr[base+1] = texcl + i0;
    g_eptr[base+2] = texcl + i1;
    g_eptr[base+3] = texcl + i2;
    if (tid == 1023) g_eptr[NN] = texcl + i3;
    if (tid == 0){
        int s = 0;
        #pragma unroll
        for (int t = 0; t < TT; t++){ g_tptr[t] = s; s += g_tcount[t]; }
        g_tptr[TT] = s;
    }
}

__global__ void scatter_k(const int* __restrict__ ntypes, const int* __restrict__ eidx,
                          const int* __restrict__ etypes){
    int i = blockIdx.x * blockDim.x + threadIdx.x;
    if (i < NN){
        int t = ntypes[i];
        g_nodes[g_tptr[t] + atomicAdd(&g_tfill[t], 1)] = i;
    } else if (i < NN + NEDGE){
        int e = i - NN;
        int tgt = eidx[NEDGE + e];
        int pos = g_eptr[tgt] + atomicAdd(&g_efill[tgt], 1);
        g_epk[pos] = (unsigned)eidx[e] | ((unsigned)etypes[e] << 12) | ((unsigned)tgt << 14);
    }
}

__global__ void __launch_bounds__(128) proj_k(
    const float* __restrict__ xq, const float* __restrict__ xk, const float* __restrict__ xv,
    const float* __restrict__ Wq, const float* __restrict__ bq,
    const float* __restrict__ Wk, const float* __restrict__ bk,
    const float* __restrict__ Wv, const float* __restrict__ bv){
    const int t = blockIdx.y;
    const int start = g_tptr[t] + blockIdx.x * 16;
    const int end = g_tptr[t+1];
    if (start >= end) return;
    const int cnt = min(16, end - start);
    __shared__ int nid[16];
    __shared__ float sq[128*17], sk[128*17], sv[128*17];
    const int f = threadIdx.x;
    if (f < 16) nid[f] = (f < cnt) ? g_nodes[start + f] : -1;
    __syncthreads();
    #pragma unroll
    for (int n = 0; n < 16; n++){
        int row = nid[n];
        float a=0.f,b=0.f,c=0.f;
        if (row >= 0){
            a = xq[(size_t)row*EE + f];
            b = xk[(size_t)row*EE + f];
            c = xv[(size_t)row*EE + f];
        }
        sq[f*17+n]=a; sk[f*17+n]=b; sv[f*17+n]=c;
    }
    __syncthreads();
    float aq[16], ak[16], av[16];
    #pragma unroll
    for (int n = 0; n < 16; n++){ aq[n]=0.f; ak[n]=0.f; av[n]=0.f; }
    const float* wq = Wq + (size_t)t*EE*EE;
    const float* wk = Wk + (size_t)t*EE*EE;
    const float* wv = Wv + (size_t)t*EE*EE;
    for (int e = 0; e < EE; e++){
        float q = wq[e*EE+f], k = wk[e*EE+f], v = wv[e*EE+f];
        #pragma unroll
        for (int n = 0; n < 16; n++){
            aq[n] = fmaf(sq[e*17+n], q, aq[n]);
            ak[n] = fmaf(sk[e*17+n], k, ak[n]);
            av[n] = fmaf(sv[e*17+n], v, av[n]);
        }
    }
    float bqv = bq[t*EE+f], bkv = bk[t*EE+f], bvv = bv[t*EE+f];
    const int fh = f >> 4, fd = f & 15;
    for (int n = 0; n < cnt; n++){
        int row = nid[n];
        size_t idx = ((size_t)fh*NN + row)*DD + fd;
        g_Qh[idx] = aq[n] + bqv;
        g_Kh[idx] = ak[n] + bkv;
        g_Vh[idx] = av[n] + bvv;
    }
}

// SMEM: S 12*4096 f32 (196608B) | qsm 16*6 u64 (768B)
#define SM_Q 196608
#define SM_TOTAL (196608 + 768)

__global__ void __launch_bounds__(TPB, 1) attn_k(const float* __restrict__ eb,
                                                 float* __restrict__ attn){
    extern __shared__ unsigned char smraw[];
    float* S   = (float*)smraw;
    u64*   qsm = (u64*)(smraw + SM_Q);

    const int tid = threadIdx.x, lane = tid & 31, w = tid >> 5;
    const int h = blockIdx.y;
    const int i0 = blockIdx.x * RR;
    const int rows = min(RR, NN - i0);
    const float* Kh = g_Kh + (size_t)h*NN*DD;

    // Q tile, pre-scaled by 1/sqrt(D); pad rows -> 0
    for (int t = tid; t < 192; t += TPB){
        int r = t >> 4, d = t & 15;
        float q = (r < rows) ? g_Qh[((size_t)h*NN + i0 + r)*DD + d] * 0.25f : 0.f;
        ((float*)qsm)[(d*6 + (r>>1))*2 + (r&1)] = q;
    }
    __syncthreads();

    // P1: scores = (Q/sqrtD) K^T ; K per-head, fully coalesced
    for (int j = tid; j < 2048; j += TPB){
        const float4* kpa = (const float4*)(Kh + (size_t)j*DD);
        const float4* kpb = (const float4*)(Kh + (size_t)(j+2048)*DD);
        float4 a0=kpa[0],a1=kpa[1],a2=kpa[2],a3=kpa[3];
        float4 b0=kpb[0],b1=kpb[1],b2=kpb[2],b3=kpb[3];
        float ka[16]={a0.x,a0.y,a0.z,a0.w,a1.x,a1.y,a1.z,a1.w,
                      a2.x,a2.y,a2.z,a2.w,a3.x,a3.y,a3.z,a3.w};
        float kb[16]={b0.x,b0.y,b0.z,b0.w,b1.x,b1.y,b1.z,b1.w,
                      b2.x,b2.y,b2.z,b2.w,b3.x,b3.y,b3.z,b3.w};
        u64 acc[6], bcc[6];
        #pragma unroll
        for (int rp = 0; rp < 6; rp++){ acc[rp]=0ull; bcc[rp]=0ull; }
        #pragma unroll
        for (int d = 0; d < 16; d++){
            u64 ka2 = pk2(ka[d], ka[d]);
            u64 kb2 = pk2(kb[d], kb[d]);
            #pragma unroll
            for (int rp = 0; rp < 6; rp++){
                u64 q2 = qsm[d*6 + rp];
                acc[rp] = ffma2(q2, ka2, acc[rp]);
                bcc[rp] = ffma2(q2, kb2, bcc[rp]);
            }
        }
        #pragma unroll
        for (int rp = 0; rp < 6; rp++){
            float x, y;
            up2(acc[rp], x, y);
            S[(2*rp)*NN + j]   = x;
            S[(2*rp+1)*NN + j] = y;
            up2(bcc[rp], x, y);
            S[(2*rp)*NN + j + 2048]   = x;
            S[(2*rp+1)*NN + j + 2048] = y;
        }
    }
    __syncthreads();

    // P2: CSR edge bias (dup-safe scatter-add)
    {
        float eb0 = eb[h], eb1 = eb[HH + h], eb2 = eb[2*HH + h];
        int e0 = g_eptr[i0], e1 = g_eptr[i0 + rows];
        for (int e = e0 + tid; e < e1; e += TPB){
            unsigned p = g_epk[e];
            int src = p & 0xFFF;
            int et  = (p >> 12) & 3;
            int r   = (int)(p >> 14) - i0;
            float b = (et == 0) ? eb0 : ((et == 1) ? eb1 : eb2);
            atomicAdd(&S[r*NN + src], b);
        }
    }
    __syncthreads();

    // P3: softmax per row (warp-per-row), write normalized attn to global only
    if (w < rows){
        float* Srow = S + (size_t)w*NN;
        float m = -1e30f;
        for (int j = lane; j < NN; j += 32) m = fmaxf(m, Srow[j]);
        m = wmax(m);
        float s = 0.f;
        for (int j = lane; j < NN; j += 32){
            float e = __expf(Srow[j] - m);
            Srow[j] = e; s += e;
        }
        s = wsum(s);
        float invs = 1.f / s;
        float* arow = attn + (size_t)h*NN*NN + (size_t)(i0+w)*NN;
        for (int j = lane; j < NN; j += 32)
            arow[j] = Srow[j] * invs;
    }
}

// AV kernel: out_h[i,:] = sum_j attn[h,i,j] * V_h[j,:]
// grid (128, 8), 256 threads = 8 warps, 4 rows/warp, V tiles of 512 rows in smem
__global__ void __launch_bounds__(256) av_k(const float* __restrict__ attn){
    __shared__ u64 vsm[512*10];   // 40960 B, stride-10 -> conflict-free LDS.128
    const int tid = threadIdx.x, lane = tid & 31, w = tid >> 5;
    const int h = blockIdx.y;
    const int i0 = blockIdx.x * 32;
    const float* Vh = g_Vh + (size_t)h*NN*DD;
    const float* arow0 = attn + (size_t)h*NN*NN + (size_t)(i0 + w*4)*NN;

    u64 acc[4][8];
    #pragma unroll
    for (int r = 0; r < 4; r++)
        #pragma unroll
        for (int dp = 0; dp < 8; dp++) acc[r][dp] = 0ull;

    for (int jt = 0; jt < NN; jt += 512){
        __syncthreads();
        for (int t = tid; t < 4096; t += 256){
            int j = t >> 3, dp = t & 7;
            float2 v2 = *(const float2*)(Vh + (size_t)(jt+j)*DD + dp*2);
            vsm[j*10 + dp] = pk2(v2.x, v2.y);
        }
        __syncthreads();
        #pragma unroll
        for (int jj = 0; jj < 16; jj++){
            int j = jj*32 + lane;
            const unsigned char* vb = (const unsigned char*)vsm + j*80;
            u64 vv[8];
            #pragma unroll
            for (int q = 0; q < 4; q++){
                float4 f4 = *(const float4*)(vb + q*16);
                vv[2*q]   = pk2(f4.x, f4.y);
                vv[2*q+1] = pk2(f4.z, f4.w);
            }
            #pragma unroll
            for (int r = 0; r < 4; r++){
                float p = arow0[(size_t)r*NN + jt + j];
                u64 pp = pk2(p, p);
                #pragma unroll
                for (int dp = 0; dp < 8; dp++)
                    acc[r][dp] = ffma2(vv[dp], pp, acc[r][dp]);
            }
        }
    }
    #pragma unroll
    for (int r = 0; r < 4; r++){
        float fv[16];
        #pragma unroll
        for (int dp = 0; dp < 8; dp++) up2(acc[r][dp], fv[2*dp], fv[2*dp+1]);
        float outv = 0.f;
        #pragma unroll
        for (int d = 0; d < 16; d++){
            float sv = wsum(fv[d]);
            if (lane == d) outv = sv;
        }
        if (lane < 16) g_O[(size_t)(i0 + w*4 + r)*EE + h*DD + lane] = outv;
    }
}

__global__ void __launch_bounds__(128) out_k(const float* __restrict__ Wo,
                                             const float* __restrict__ bo,
                                             float* __restrict__ out){
    __shared__ float s[32*129];
    const int f = threadIdx.x;
    const int r0 = blockIdx.x * 32;
    for (int t = f; t < 32*128; t += 128){
        int n = t >> 7, e = t & 127;
        s[n*129 + e] = g_O[(size_t)(r0+n)*EE + e];
    }
    __syncthreads();
    float acc[32];
    float bv = bo[f];
    #pragma unroll
    for (int n = 0; n < 32; n++) acc[n] = bv;
    for (int e = 0; e < 128; e++){
        float wv = Wo[e*EE + f];
        #pragma unroll
        for (int n = 0; n < 32; n++) acc[n] = fmaf(s[n*129 + e], wv, acc[n]);
    }
    #pragma unroll
    for (int n = 0; n < 32; n++) out[(size_t)(r0+n)*EE + f] = acc[n];
}

extern "C" void kernel_launch(void* const* d_in, const int* in_sizes, int n_in,
                              void* d_out, int out_size){
    const float* query = (const float*)d_in[0];
    const float* key_  = (const float*)d_in[1];
    const float* value = (const float*)d_in[2];
    const float* Wq = (const float*)d_in[3];
    const float* bq = (const float*)d_in[4];
    const float* Wk = (const float*)d_in[5];
    const float* bk = (const float*)d_in[6];
    const float* Wv = (const float*)d_in[7];
    const float* bv = (const float*)d_in[8];
    const float* eb = (const float*)d_in[9];
    const float* Wo = (const float*)d_in[10];
    const float* bo = (const float*)d_in[11];
    const int* ntypes = (const int*)d_in[12];
    const int* eidx   = (const int*)d_in[13];
    const int* etypes = (const int*)d_in[14];
    float* out  = (float*)d_out;
    float* attn = out + (size_t)NN*EE;

    static bool attr_set = false;
    if (!attr_set){
        cudaFuncSetAttribute(attn_k, cudaFuncAttributeMaxDynamicSharedMemorySize, SM_TOTAL);
        attr_set = true;
    }

    zero_k<<<(2*NN + 2*TT + 255)/256, 256>>>();
    count_k<<<(NN + NEDGE + 255)/256, 256>>>(ntypes, eidx);
    scan_k<<<1, 1024>>>();
    scatter_k<<<(NN + NEDGE + 255)/256, 256>>>(ntypes, eidx, etypes);
    proj_k<<<dim3((NN + 15)/16, TT), 128>>>(query, key_, value, Wq, bq, Wk, bk, Wv, bv);
    attn_k<<<dim3((NN + RR - 1)/RR, HH), TPB, SM_TOTAL>>>(eb, attn);
    av_k<<<dim3(NN/32, HH), 256>>>(attn);
    out_k<<<NN/32, 128>>>(Wo, bo, out);
}